// round 6
// baseline (speedup 1.0000x reference)
#include <cuda_runtime.h>
#include <cuda_bf16.h>
#include <cstdint>

// Problem constants
#define NN 100000
#define EE 1600000
#define HH 128
#define BB 4096
#define CTX 20

// Scratch (allocation-free). 16B alignment for float4 paths.
__device__ __align__(16) int   g_cnt[NN];
__device__ __align__(16) int   g_rowptr[NN + 1];
__device__ __align__(16) int   g_cursor[NN];
__device__ __align__(16) int   g_esrc[EE];
__device__ __align__(16) float g_ew[EE];
__device__ __align__(16) float g_h1[NN * HH];
__device__ __align__(16) float g_h2[NN * HH];

// ---------- packed f32x2 helpers ----------
__device__ __forceinline__ unsigned long long pk2(float x) {
    unsigned long long r;
    asm("mov.b64 %0, {%1, %1};" : "=l"(r) : "f"(x));
    return r;
}
__device__ __forceinline__ unsigned long long ffma2(unsigned long long a,
                                                    unsigned long long b,
                                                    unsigned long long c) {
    unsigned long long d;
    asm("fma.rn.f32x2 %0, %1, %2, %3;" : "=l"(d) : "l"(a), "l"(b), "l"(c));
    return d;
}
__device__ __forceinline__ void unpk2(unsigned long long v, float& lo, float& hi) {
    asm("mov.b64 {%0, %1}, %2;" : "=f"(lo), "=f"(hi) : "l"(v));
}

// ---------- CSR build: histogram ----------
__global__ void hist_kernel(const int* __restrict__ dst) {
    int i = blockIdx.x * blockDim.x + threadIdx.x;
    int stride = gridDim.x * blockDim.x;
    for (; i < EE; i += stride)
        atomicAdd(&g_cnt[dst[i]], 1);
}

// ---------- CSR build: single-block exclusive scan over 100k counts ----------
#define SCAN_T 1024
#define SCAN_CHUNK 98   // 1024*98 >= 100000
__global__ void scan_kernel() {
    __shared__ int part[SCAN_T];
    int t = threadIdx.x;
    int lo = t * SCAN_CHUNK;
    int hi = lo + SCAN_CHUNK; if (hi > NN) hi = NN;
    int s = 0;
    for (int i = lo; i < hi; i++) s += g_cnt[i];
    part[t] = s;
    __syncthreads();
    // Kogge-Stone inclusive scan
    for (int off = 1; off < SCAN_T; off <<= 1) {
        int v = (t >= off) ? part[t - off] : 0;
        __syncthreads();
        part[t] += v;
        __syncthreads();
    }
    int run = (t > 0) ? part[t - 1] : 0;
    for (int i = lo; i < hi; i++) {
        int c = g_cnt[i];
        g_rowptr[i] = run;
        g_cursor[i] = run;
        run += c;
    }
    if (t == SCAN_T - 1) g_rowptr[NN] = part[SCAN_T - 1];
}

// ---------- CSR build: scatter edges sorted by dst (SoA: src, w) ----------
__global__ void scatter_kernel(const int* __restrict__ src,
                               const int* __restrict__ dst,
                               const float* __restrict__ w) {
    int i = blockIdx.x * blockDim.x + threadIdx.x;
    int stride = gridDim.x * blockDim.x;
    for (; i < EE; i += stride) {
        int d = dst[i];
        int pos = atomicAdd(&g_cursor[d], 1);
        g_esrc[pos] = src[i];
        g_ew[pos]   = w[i];
    }
}

// ---------- fused GIN layer: CSR-aggregate + combine + GEMM + activation ----
// Block = 64 nodes, 256 threads (8 warps, 8 nodes/warp).
// out = act(((1+eps)*x + agg/deg) @ W^T + b)
#define GEMM_SMEM ((128 * 66 + 128 * 132) * 4)

template <int RELU, int ZERO0>
__global__ __launch_bounds__(256)
void gin_fused(const float* __restrict__ x,
               const float* __restrict__ W,
               const float* __restrict__ b,
               const float* __restrict__ eps, int epsidx,
               float* __restrict__ out) {
    extern __shared__ float sm[];
    float* Zt = sm;                // [128 k][66] nodes transposed, pad 2
    float* Wt = sm + 128 * 66;     // [128 k][132] out-channels transposed, pad 4

    int tid = threadIdx.x;
    int base = blockIdx.x * 64;
    int rows = NN - base; if (rows > 64) rows = 64;
    float ep = 1.0f + __ldg(&eps[epsidx]);

    // W transpose into smem: Wt[k][c] = W[c][k]
    for (int i = tid; i < 128 * 128; i += 256) {
        int c = i >> 7, k = i & 127;
        Wt[k * 132 + c] = W[i];
    }

    // CSR aggregation straight into the Z tile (no global agg buffer).
    int lane = tid & 31, wrp = tid >> 5;
#pragma unroll 1
    for (int q = 0; q < 8; q++) {
        int r = wrp * 8 + q;
        int node = base + r;
        float z0 = 0.f, z1 = 0.f, z2 = 0.f, z3 = 0.f;
        if (r < rows) {
            int e0 = __ldg(&g_rowptr[node]);
            int e1 = __ldg(&g_rowptr[node + 1]);
            float rdeg = 1.0f / fmaxf((float)(e1 - e0), 1.0f);
            float4 a0 = {0.f, 0.f, 0.f, 0.f};
            float4 a1 = {0.f, 0.f, 0.f, 0.f};
            int e = e0;
            // dual accumulators: 2 outstanding gather rows
            for (; e + 1 < e1; e += 2) {
                int   s0 = __ldg(&g_esrc[e]);
                int   s1 = __ldg(&g_esrc[e + 1]);
                float w0 = __ldg(&g_ew[e]);
                float w1 = __ldg(&g_ew[e + 1]);
                float4 v0 = __ldg(reinterpret_cast<const float4*>(x + (size_t)s0 * HH) + lane);
                float4 v1 = __ldg(reinterpret_cast<const float4*>(x + (size_t)s1 * HH) + lane);
                a0.x = fmaf(w0, v0.x, a0.x); a0.y = fmaf(w0, v0.y, a0.y);
                a0.z = fmaf(w0, v0.z, a0.z); a0.w = fmaf(w0, v0.w, a0.w);
                a1.x = fmaf(w1, v1.x, a1.x); a1.y = fmaf(w1, v1.y, a1.y);
                a1.z = fmaf(w1, v1.z, a1.z); a1.w = fmaf(w1, v1.w, a1.w);
            }
            if (e < e1) {
                int   s0 = __ldg(&g_esrc[e]);
                float w0 = __ldg(&g_ew[e]);
                float4 v0 = __ldg(reinterpret_cast<const float4*>(x + (size_t)s0 * HH) + lane);
                a0.x = fmaf(w0, v0.x, a0.x); a0.y = fmaf(w0, v0.y, a0.y);
                a0.z = fmaf(w0, v0.z, a0.z); a0.w = fmaf(w0, v0.w, a0.w);
            }
            float4 xv = __ldg(reinterpret_cast<const float4*>(x + (size_t)node * HH) + lane);
            z0 = fmaf(ep, xv.x, (a0.x + a1.x) * rdeg);
            z1 = fmaf(ep, xv.y, (a0.y + a1.y) * rdeg);
            z2 = fmaf(ep, xv.z, (a0.z + a1.z) * rdeg);
            z3 = fmaf(ep, xv.w, (a0.w + a1.w) * rdeg);
        }
        int k0 = lane * 4;
        Zt[(k0 + 0) * 66 + r] = z0;
        Zt[(k0 + 1) * 66 + r] = z1;
        Zt[(k0 + 2) * 66 + r] = z2;
        Zt[(k0 + 3) * 66 + r] = z3;
    }
    __syncthreads();

    // GEMM: 8x4 register tile per thread, packed f32x2
    int tx = tid & 31, ty = tid >> 5;
    int c0 = tx * 4, r0 = ty * 8;
    unsigned long long acc[4][4];
#pragma unroll
    for (int p = 0; p < 4; p++)
#pragma unroll
        for (int j = 0; j < 4; j++) acc[p][j] = 0ULL;

#pragma unroll 4
    for (int k = 0; k < 128; k++) {
        float4 wv = *reinterpret_cast<const float4*>(&Wt[k * 132 + c0]);
        unsigned long long b0 = pk2(wv.x), b1 = pk2(wv.y), b2 = pk2(wv.z), b3 = pk2(wv.w);
        const unsigned long long* az =
            reinterpret_cast<const unsigned long long*>(&Zt[k * 66 + r0]);
        unsigned long long a0 = az[0], a1 = az[1], a2 = az[2], a3 = az[3];
        acc[0][0] = ffma2(a0, b0, acc[0][0]); acc[0][1] = ffma2(a0, b1, acc[0][1]);
        acc[0][2] = ffma2(a0, b2, acc[0][2]); acc[0][3] = ffma2(a0, b3, acc[0][3]);
        acc[1][0] = ffma2(a1, b0, acc[1][0]); acc[1][1] = ffma2(a1, b1, acc[1][1]);
        acc[1][2] = ffma2(a1, b2, acc[1][2]); acc[1][3] = ffma2(a1, b3, acc[1][3]);
        acc[2][0] = ffma2(a2, b0, acc[2][0]); acc[2][1] = ffma2(a2, b1, acc[2][1]);
        acc[2][2] = ffma2(a2, b2, acc[2][2]); acc[2][3] = ffma2(a2, b3, acc[2][3]);
        acc[3][0] = ffma2(a3, b0, acc[3][0]); acc[3][1] = ffma2(a3, b1, acc[3][1]);
        acc[3][2] = ffma2(a3, b2, acc[3][2]); acc[3][3] = ffma2(a3, b3, acc[3][3]);
    }

    float4 bv = *reinterpret_cast<const float4*>(&b[c0]);
    float bb[4] = {bv.x, bv.y, bv.z, bv.w};
#pragma unroll
    for (int p = 0; p < 4; p++) {
        float lo[4], hi[4];
#pragma unroll
        for (int j = 0; j < 4; j++) unpk2(acc[p][j], lo[j], hi[j]);
        int r = r0 + 2 * p;
#pragma unroll
        for (int half = 0; half < 2; half++) {
            int rr = r + half;
            if (rr < rows) {
                int node = base + rr;
                float v0 = (half ? hi[0] : lo[0]) + bb[0];
                float v1 = (half ? hi[1] : lo[1]) + bb[1];
                float v2 = (half ? hi[2] : lo[2]) + bb[2];
                float v3 = (half ? hi[3] : lo[3]) + bb[3];
                if (RELU) { v0 = fmaxf(v0, 0.f); v1 = fmaxf(v1, 0.f);
                            v2 = fmaxf(v2, 0.f); v3 = fmaxf(v3, 0.f); }
                if (ZERO0 && node == 0) { v0 = v1 = v2 = v3 = 0.f; }
                float4 o; o.x = v0; o.y = v1; o.z = v2; o.w = v3;
                *reinterpret_cast<float4*>(out + (size_t)node * HH + c0) = o;
            }
        }
    }
}

// ---------- MLP head: 16 batch rows per block, 128 threads ----------
// indices are INT32 (JAX x64 disabled downcasts the declared int64).
#define MLP_IND_BYTES 1536
#define MLP_SMEM (MLP_IND_BYTES + (384 * 18 + 128 * 65 + 16 * 128 + 64 * 129 + 16 * 64) * 4)

__global__ void mlp_kernel(const float* __restrict__ x,
                           const int* __restrict__ ind,
                           const float* __restrict__ Wc1, const float* __restrict__ bc1,
                           const float* __restrict__ Wc2, const float* __restrict__ bc2,
                           const float* __restrict__ Wc3, const float* __restrict__ bc3,
                           float* __restrict__ out) {
    extern __shared__ char smraw[];
    int* inds = reinterpret_cast<int*>(smraw);
    float* Yt   = reinterpret_cast<float*>(smraw + MLP_IND_BYTES); // [384][18]
    float* Wcs  = Yt + 384 * 18;                                   // [128][65]
    float* h1s  = Wcs + 128 * 65;                                  // [16][128]
    float* Wc2s = h1s + 16 * 128;                                  // [64][129]
    float* h2s  = Wc2s + 64 * 129;                                 // [16][64]

    int tid = threadIdx.x;
    int rb0 = blockIdx.x * 16;

    for (int i = tid; i < 16 * 23; i += 128)
        inds[i] = ind[(size_t)rb0 * 23 + i];
    __syncthreads();

    // gather: Yt[k][r]  (k: 0-127 ing1, 128-255 ing2, 256-383 ctx mean)
    int t = tid;
    for (int r = 0; r < 16; r++) {
        int i0 = inds[r * 23 + 0];
        int i1 = inds[r * 23 + 1];
        Yt[t * 18 + r]         = __ldg(&x[(size_t)i0 * HH + t]);
        Yt[(128 + t) * 18 + r] = __ldg(&x[(size_t)i1 * HH + t]);
        float s = 0.0f; int cnt = 0;
#pragma unroll
        for (int j = 0; j < CTX; j++) {
            int cj = inds[r * 23 + 3 + j];
            s += __ldg(&x[(size_t)cj * HH + t]);
            cnt += (cj > 0);
        }
        if (cnt < 1) cnt = 1;
        Yt[(256 + t) * 18 + r] = s * (1.0f / (float)cnt);
    }

    // C1: 384 -> 128, relu (thread = out channel, f32x2 over row pairs)
    int c = tid;
    unsigned long long acc2[8];
#pragma unroll
    for (int p = 0; p < 8; p++) acc2[p] = 0ULL;

    for (int kc = 0; kc < 6; kc++) {
        __syncthreads();
        for (int i = tid; i < 128 * 64; i += 128) {
            int cc = i >> 6, kk = i & 63;
            Wcs[cc * 65 + kk] = Wc1[(size_t)cc * 384 + kc * 64 + kk];
        }
        __syncthreads();
#pragma unroll 4
        for (int kk = 0; kk < 64; kk++) {
            int k = kc * 64 + kk;
            unsigned long long w2 = pk2(Wcs[c * 65 + kk]);
            const unsigned long long* ay =
                reinterpret_cast<const unsigned long long*>(&Yt[k * 18]);
#pragma unroll
            for (int p = 0; p < 8; p++) acc2[p] = ffma2(ay[p], w2, acc2[p]);
        }
    }
    {
        float bb = __ldg(&bc1[c]);
#pragma unroll
        for (int p = 0; p < 8; p++) {
            float lo, hi;
            unpk2(acc2[p], lo, hi);
            h1s[(2 * p) * 128 + c]     = fmaxf(lo + bb, 0.0f);
            h1s[(2 * p + 1) * 128 + c] = fmaxf(hi + bb, 0.0f);
        }
    }
    __syncthreads();

    // C2: 128 -> 64, relu
    for (int i = tid; i < 64 * 128; i += 128) {
        int cc = i >> 7, kk = i & 127;
        Wc2s[cc * 129 + kk] = Wc2[i];
    }
    __syncthreads();
    {
        int c2 = tid & 63;
        int rh = tid >> 6;
        float acc[8];
#pragma unroll
        for (int q = 0; q < 8; q++) acc[q] = 0.0f;
#pragma unroll 4
        for (int k = 0; k < 128; k++) {
            float wv = Wc2s[c2 * 129 + k];
#pragma unroll
            for (int q = 0; q < 8; q++)
                acc[q] += h1s[(q * 2 + rh) * 128 + k] * wv;
        }
        float b2v = __ldg(&bc2[c2]);
#pragma unroll
        for (int q = 0; q < 8; q++)
            h2s[(q * 2 + rh) * 64 + c2] = fmaxf(acc[q] + b2v, 0.0f);
    }
    __syncthreads();

    // C3: 64 -> 1
    if (tid < 16) {
        float a = __ldg(&bc3[0]);
#pragma unroll 4
        for (int k = 0; k < 64; k++)
            a += h2s[tid * 64 + k] * __ldg(&Wc3[k]);
        out[rb0 + tid] = a;
    }
}

// ---------- launcher ----------
extern "C" void kernel_launch(void* const* d_in, const int* in_sizes, int n_in,
                              void* d_out, int out_size) {
    const int*   indices = (const int*)d_in[0];   // int32 (JAX x64 disabled)
    const int*   src  = (const int*)d_in[1];
    const int*   dst  = (const int*)d_in[2];
    const float* w    = (const float*)d_in[3];
    const float* nd   = (const float*)d_in[4];
    const float* W1   = (const float*)d_in[5];
    const float* b1   = (const float*)d_in[6];
    const float* W2   = (const float*)d_in[7];
    const float* b2   = (const float*)d_in[8];
    const float* eps  = (const float*)d_in[9];
    const float* Wc1  = (const float*)d_in[10];
    const float* bc1  = (const float*)d_in[11];
    const float* Wc2  = (const float*)d_in[12];
    const float* bc2  = (const float*)d_in[13];
    const float* Wc3  = (const float*)d_in[14];
    const float* bc3  = (const float*)d_in[15];
    float* out = (float*)d_out;

    cudaFuncSetAttribute(gin_fused<1, 0>, cudaFuncAttributeMaxDynamicSharedMemorySize, GEMM_SMEM);
    cudaFuncSetAttribute(gin_fused<0, 1>, cudaFuncAttributeMaxDynamicSharedMemorySize, GEMM_SMEM);
    cudaFuncSetAttribute(mlp_kernel, cudaFuncAttributeMaxDynamicSharedMemorySize, MLP_SMEM);

    float *h1p, *h2p;
    int *cntp;
    cudaGetSymbolAddress((void**)&h1p, g_h1);
    cudaGetSymbolAddress((void**)&h2p, g_h2);
    cudaGetSymbolAddress((void**)&cntp, g_cnt);

    // CSR build (identical for both layers)
    cudaMemsetAsync(cntp, 0, NN * sizeof(int));
    hist_kernel<<<1024, 256>>>(dst);
    scan_kernel<<<1, SCAN_T>>>();
    scatter_kernel<<<2048, 256>>>(src, dst, w);

    const int gemm_blocks = (NN + 63) / 64;

    // layer 1 (agg fused into GEMM)
    gin_fused<1, 0><<<gemm_blocks, 256, GEMM_SMEM>>>(nd, W1, b1, eps, 0, h1p);
    // layer 2
    gin_fused<0, 1><<<gemm_blocks, 256, GEMM_SMEM>>>(h1p, W2, b2, eps, 1, h2p);

    // head
    mlp_kernel<<<BB / 16, 128, MLP_SMEM>>>(h2p, indices, Wc1, bc1, Wc2, bc2, Wc3, bc3, out);
}

// round 10
// speedup vs baseline: 1.3209x; 1.3209x over previous
#include <cuda_runtime.h>
#include <cuda_bf16.h>
#include <cstdint>

// Problem constants
#define NN 100000
#define EE 1600000
#define HH 128
#define BB 4096
#define CTX 20

// Scratch (allocation-free). 16B alignment for vector paths.
__device__ __align__(16) int  g_cnt[NN];
__device__ __align__(16) int  g_rowptr[NN + 1];
__device__ __align__(16) int  g_cursor[NN];
__device__ __align__(16) int2 g_edge[EE];      // {src, w bits} packed
__device__ __align__(16) float g_h1[NN * HH];
__device__ __align__(16) float g_h2[NN * HH];

// ---------- packed f32x2 helpers ----------
__device__ __forceinline__ unsigned long long pk2(float x) {
    unsigned long long r;
    asm("mov.b64 %0, {%1, %1};" : "=l"(r) : "f"(x));
    return r;
}
__device__ __forceinline__ unsigned long long ffma2(unsigned long long a,
                                                    unsigned long long b,
                                                    unsigned long long c) {
    unsigned long long d;
    asm("fma.rn.f32x2 %0, %1, %2, %3;" : "=l"(d) : "l"(a), "l"(b), "l"(c));
    return d;
}
__device__ __forceinline__ void unpk2(unsigned long long v, float& lo, float& hi) {
    asm("mov.b64 {%0, %1}, %2;" : "=f"(lo), "=f"(hi) : "l"(v));
}

// ---------- CSR build: histogram ----------
__global__ void hist_kernel(const int* __restrict__ dst) {
    int i = blockIdx.x * blockDim.x + threadIdx.x;
    int stride = gridDim.x * blockDim.x;
    for (; i < EE; i += stride)
        atomicAdd(&g_cnt[dst[i]], 1);
}

// ---------- CSR build: single-block exclusive scan over 100k counts ----------
#define SCAN_T 1024
#define SCAN_CHUNK 98   // 1024*98 >= 100000
__global__ void scan_kernel() {
    __shared__ int part[SCAN_T];
    int t = threadIdx.x;
    int lo = t * SCAN_CHUNK;
    int hi = lo + SCAN_CHUNK; if (hi > NN) hi = NN;
    int s = 0;
    for (int i = lo; i < hi; i++) s += g_cnt[i];
    part[t] = s;
    __syncthreads();
    for (int off = 1; off < SCAN_T; off <<= 1) {
        int v = (t >= off) ? part[t - off] : 0;
        __syncthreads();
        part[t] += v;
        __syncthreads();
    }
    int run = (t > 0) ? part[t - 1] : 0;
    for (int i = lo; i < hi; i++) {
        int c = g_cnt[i];
        g_rowptr[i] = run;
        g_cursor[i] = run;
        run += c;
    }
    if (t == SCAN_T - 1) g_rowptr[NN] = part[SCAN_T - 1];
}

// ---------- CSR build: scatter packed edges sorted by dst ----------
__global__ void scatter_kernel(const int* __restrict__ src,
                               const int* __restrict__ dst,
                               const float* __restrict__ w) {
    int i = blockIdx.x * blockDim.x + threadIdx.x;
    int stride = gridDim.x * blockDim.x;
    for (; i < EE; i += stride) {
        int d = dst[i];
        int pos = atomicAdd(&g_cursor[d], 1);
        int2 e; e.x = src[i]; e.y = __float_as_int(w[i]);
        g_edge[pos] = e;
    }
}

// ---------- fused GIN layer: CSR-aggregate + combine + K-chunked GEMM ------
// Block = 64 nodes, 256 threads (8 warps, 8 nodes/warp).
// smem = Zt 33KB + W-chunk 16.5KB = 50.7KB -> 4 CTAs/SM.
#define KCH 32
#define GEMM_SMEM ((128 * 66 + KCH * 132) * 4)

template <int RELU, int ZERO0>
__global__ __launch_bounds__(256, 4)
void gin_fused(const float* __restrict__ x,
               const float* __restrict__ W,
               const float* __restrict__ b,
               const float* __restrict__ eps, int epsidx,
               float* __restrict__ out) {
    extern __shared__ float sm[];
    float* Zt = sm;                 // [128 k][66] nodes transposed, pad 2
    float* Wc = sm + 128 * 66;      // [KCH][132] chunk of W^T, pad 4

    int tid = threadIdx.x;
    int base = blockIdx.x * 64;
    int rows = NN - base; if (rows > 64) rows = 64;
    float ep = 1.0f + __ldg(&eps[epsidx]);

    // CSR aggregation straight into the Z tile.
    int lane = tid & 31, wrp = tid >> 5;
#pragma unroll 1
    for (int q = 0; q < 8; q++) {
        int r = wrp * 8 + q;
        int node = base + r;
        float z0 = 0.f, z1 = 0.f, z2 = 0.f, z3 = 0.f;
        if (r < rows) {
            int e0 = __ldg(&g_rowptr[node]);
            int e1 = __ldg(&g_rowptr[node + 1]);
            float rdeg = 1.0f / fmaxf((float)(e1 - e0), 1.0f);
            float4 a0 = {0.f,0.f,0.f,0.f}, a1 = a0, a2 = a0, a3 = a0;
            int e = e0;
            // 4 independent accumulators -> 4 outstanding gather rows
            for (; e + 3 < e1; e += 4) {
                int2 E0 = __ldg(&g_edge[e]);
                int2 E1 = __ldg(&g_edge[e + 1]);
                int2 E2 = __ldg(&g_edge[e + 2]);
                int2 E3 = __ldg(&g_edge[e + 3]);
                float4 v0 = __ldg(reinterpret_cast<const float4*>(x + (size_t)E0.x * HH) + lane);
                float4 v1 = __ldg(reinterpret_cast<const float4*>(x + (size_t)E1.x * HH) + lane);
                float4 v2 = __ldg(reinterpret_cast<const float4*>(x + (size_t)E2.x * HH) + lane);
                float4 v3 = __ldg(reinterpret_cast<const float4*>(x + (size_t)E3.x * HH) + lane);
                float w0 = __int_as_float(E0.y), w1 = __int_as_float(E1.y);
                float w2 = __int_as_float(E2.y), w3 = __int_as_float(E3.y);
                a0.x = fmaf(w0, v0.x, a0.x); a0.y = fmaf(w0, v0.y, a0.y);
                a0.z = fmaf(w0, v0.z, a0.z); a0.w = fmaf(w0, v0.w, a0.w);
                a1.x = fmaf(w1, v1.x, a1.x); a1.y = fmaf(w1, v1.y, a1.y);
                a1.z = fmaf(w1, v1.z, a1.z); a1.w = fmaf(w1, v1.w, a1.w);
                a2.x = fmaf(w2, v2.x, a2.x); a2.y = fmaf(w2, v2.y, a2.y);
                a2.z = fmaf(w2, v2.z, a2.z); a2.w = fmaf(w2, v2.w, a2.w);
                a3.x = fmaf(w3, v3.x, a3.x); a3.y = fmaf(w3, v3.y, a3.y);
                a3.z = fmaf(w3, v3.z, a3.z); a3.w = fmaf(w3, v3.w, a3.w);
            }
            for (; e < e1; e++) {
                int2 E0 = __ldg(&g_edge[e]);
                float w0 = __int_as_float(E0.y);
                float4 v0 = __ldg(reinterpret_cast<const float4*>(x + (size_t)E0.x * HH) + lane);
                a0.x = fmaf(w0, v0.x, a0.x); a0.y = fmaf(w0, v0.y, a0.y);
                a0.z = fmaf(w0, v0.z, a0.z); a0.w = fmaf(w0, v0.w, a0.w);
            }
            float4 xv = __ldg(reinterpret_cast<const float4*>(x + (size_t)node * HH) + lane);
            z0 = fmaf(ep, xv.x, ((a0.x + a1.x) + (a2.x + a3.x)) * rdeg);
            z1 = fmaf(ep, xv.y, ((a0.y + a1.y) + (a2.y + a3.y)) * rdeg);
            z2 = fmaf(ep, xv.z, ((a0.z + a1.z) + (a2.z + a3.z)) * rdeg);
            z3 = fmaf(ep, xv.w, ((a0.w + a1.w) + (a2.w + a3.w)) * rdeg);
        }
        int k0 = lane * 4;
        Zt[(k0 + 0) * 66 + r] = z0;
        Zt[(k0 + 1) * 66 + r] = z1;
        Zt[(k0 + 2) * 66 + r] = z2;
        Zt[(k0 + 3) * 66 + r] = z3;
    }
    __syncthreads();

    // GEMM: K streamed in 4 chunks of 32; 8x4 register tile, packed f32x2
    int tx = tid & 31, ty = tid >> 5;
    int c0 = tx * 4, r0 = ty * 8;
    unsigned long long acc[4][4];
#pragma unroll
    for (int p = 0; p < 4; p++)
#pragma unroll
        for (int j = 0; j < 4; j++) acc[p][j] = 0ULL;

    for (int kc = 0; kc < 128 / KCH; kc++) {
        // stage W^T chunk: Wc[kk][c] = W[c][kc*KCH+kk]; warp-coalesced global reads
        for (int i = tid; i < 128 * KCH; i += 256) {
            int c = i >> 5, kk = i & 31;
            Wc[kk * 132 + c] = W[c * 128 + kc * KCH + kk];
        }
        __syncthreads();
#pragma unroll 4
        for (int kk = 0; kk < KCH; kk++) {
            int k = kc * KCH + kk;
            float4 wv = *reinterpret_cast<const float4*>(&Wc[kk * 132 + c0]);
            unsigned long long b0 = pk2(wv.x), b1 = pk2(wv.y), b2 = pk2(wv.z), b3 = pk2(wv.w);
            const unsigned long long* az =
                reinterpret_cast<const unsigned long long*>(&Zt[k * 66 + r0]);
            unsigned long long a0 = az[0], a1 = az[1], a2 = az[2], a3 = az[3];
            acc[0][0] = ffma2(a0, b0, acc[0][0]); acc[0][1] = ffma2(a0, b1, acc[0][1]);
            acc[0][2] = ffma2(a0, b2, acc[0][2]); acc[0][3] = ffma2(a0, b3, acc[0][3]);
            acc[1][0] = ffma2(a1, b0, acc[1][0]); acc[1][1] = ffma2(a1, b1, acc[1][1]);
            acc[1][2] = ffma2(a1, b2, acc[1][2]); acc[1][3] = ffma2(a1, b3, acc[1][3]);
            acc[2][0] = ffma2(a2, b0, acc[2][0]); acc[2][1] = ffma2(a2, b1, acc[2][1]);
            acc[2][2] = ffma2(a2, b2, acc[2][2]); acc[2][3] = ffma2(a2, b3, acc[2][3]);
            acc[3][0] = ffma2(a3, b0, acc[3][0]); acc[3][1] = ffma2(a3, b1, acc[3][1]);
            acc[3][2] = ffma2(a3, b2, acc[3][2]); acc[3][3] = ffma2(a3, b3, acc[3][3]);
        }
        __syncthreads();
    }

    float4 bv = *reinterpret_cast<const float4*>(&b[c0]);
    float bb[4] = {bv.x, bv.y, bv.z, bv.w};
#pragma unroll
    for (int p = 0; p < 4; p++) {
        float lo[4], hi[4];
#pragma unroll
        for (int j = 0; j < 4; j++) unpk2(acc[p][j], lo[j], hi[j]);
        int r = r0 + 2 * p;
#pragma unroll
        for (int half = 0; half < 2; half++) {
            int rr = r + half;
            if (rr < rows) {
                int node = base + rr;
                float v0 = (half ? hi[0] : lo[0]) + bb[0];
                float v1 = (half ? hi[1] : lo[1]) + bb[1];
                float v2 = (half ? hi[2] : lo[2]) + bb[2];
                float v3 = (half ? hi[3] : lo[3]) + bb[3];
                if (RELU) { v0 = fmaxf(v0, 0.f); v1 = fmaxf(v1, 0.f);
                            v2 = fmaxf(v2, 0.f); v3 = fmaxf(v3, 0.f); }
                if (ZERO0 && node == 0) { v0 = v1 = v2 = v3 = 0.f; }
                float4 o; o.x = v0; o.y = v1; o.z = v2; o.w = v3;
                *reinterpret_cast<float4*>(out + (size_t)node * HH + c0) = o;
            }
        }
    }
}

// ---------- MLP head: 16 batch rows per block, 128 threads ----------
// indices are INT32 (JAX x64 disabled downcasts the declared int64).
#define MLP_IND_BYTES 1536
#define MLP_SMEM (MLP_IND_BYTES + (384 * 18 + 128 * 65 + 16 * 128 + 64 * 129 + 16 * 64) * 4)

__global__ void mlp_kernel(const float* __restrict__ x,
                           const int* __restrict__ ind,
                           const float* __restrict__ Wc1, const float* __restrict__ bc1,
                           const float* __restrict__ Wc2, const float* __restrict__ bc2,
                           const float* __restrict__ Wc3, const float* __restrict__ bc3,
                           float* __restrict__ out) {
    extern __shared__ char smraw[];
    int* inds = reinterpret_cast<int*>(smraw);
    float* Yt   = reinterpret_cast<float*>(smraw + MLP_IND_BYTES); // [384][18]
    float* Wcs  = Yt + 384 * 18;                                   // [128][65]
    float* h1s  = Wcs + 128 * 65;                                  // [16][128]
    float* Wc2s = h1s + 16 * 128;                                  // [64][129]
    float* h2s  = Wc2s + 64 * 129;                                 // [16][64]

    int tid = threadIdx.x;
    int rb0 = blockIdx.x * 16;

    for (int i = tid; i < 16 * 23; i += 128)
        inds[i] = ind[(size_t)rb0 * 23 + i];
    __syncthreads();

    int t = tid;
    for (int r = 0; r < 16; r++) {
        int i0 = inds[r * 23 + 0];
        int i1 = inds[r * 23 + 1];
        Yt[t * 18 + r]         = __ldg(&x[(size_t)i0 * HH + t]);
        Yt[(128 + t) * 18 + r] = __ldg(&x[(size_t)i1 * HH + t]);
        float s = 0.0f; int cnt = 0;
#pragma unroll
        for (int j = 0; j < CTX; j++) {
            int cj = inds[r * 23 + 3 + j];
            s += __ldg(&x[(size_t)cj * HH + t]);
            cnt += (cj > 0);
        }
        if (cnt < 1) cnt = 1;
        Yt[(256 + t) * 18 + r] = s * (1.0f / (float)cnt);
    }

    // C1: 384 -> 128, relu
    int c = tid;
    unsigned long long acc2[8];
#pragma unroll
    for (int p = 0; p < 8; p++) acc2[p] = 0ULL;

    for (int kc = 0; kc < 6; kc++) {
        __syncthreads();
        for (int i = tid; i < 128 * 64; i += 128) {
            int cc = i >> 6, kk = i & 63;
            Wcs[cc * 65 + kk] = Wc1[(size_t)cc * 384 + kc * 64 + kk];
        }
        __syncthreads();
#pragma unroll 4
        for (int kk = 0; kk < 64; kk++) {
            int k = kc * 64 + kk;
            unsigned long long w2 = pk2(Wcs[c * 65 + kk]);
            const unsigned long long* ay =
                reinterpret_cast<const unsigned long long*>(&Yt[k * 18]);
#pragma unroll
            for (int p = 0; p < 8; p++) acc2[p] = ffma2(ay[p], w2, acc2[p]);
        }
    }
    {
        float bb = __ldg(&bc1[c]);
#pragma unroll
        for (int p = 0; p < 8; p++) {
            float lo, hi;
            unpk2(acc2[p], lo, hi);
            h1s[(2 * p) * 128 + c]     = fmaxf(lo + bb, 0.0f);
            h1s[(2 * p + 1) * 128 + c] = fmaxf(hi + bb, 0.0f);
        }
    }
    __syncthreads();

    // C2: 128 -> 64, relu
    for (int i = tid; i < 64 * 128; i += 128) {
        int cc = i >> 7, kk = i & 127;
        Wc2s[cc * 129 + kk] = Wc2[i];
    }
    __syncthreads();
    {
        int c2 = tid & 63;
        int rh = tid >> 6;
        float acc[8];
#pragma unroll
        for (int q = 0; q < 8; q++) acc[q] = 0.0f;
#pragma unroll 4
        for (int k = 0; k < 128; k++) {
            float wv = Wc2s[c2 * 129 + k];
#pragma unroll
            for (int q = 0; q < 8; q++)
                acc[q] += h1s[(q * 2 + rh) * 128 + k] * wv;
        }
        float b2v = __ldg(&bc2[c2]);
#pragma unroll
        for (int q = 0; q < 8; q++)
            h2s[(q * 2 + rh) * 64 + c2] = fmaxf(acc[q] + b2v, 0.0f);
    }
    __syncthreads();

    // C3: 64 -> 1
    if (tid < 16) {
        float a = __ldg(&bc3[0]);
#pragma unroll 4
        for (int k = 0; k < 64; k++)
            a += h2s[tid * 64 + k] * __ldg(&Wc3[k]);
        out[rb0 + tid] = a;
    }
}

// ---------- launcher ----------
extern "C" void kernel_launch(void* const* d_in, const int* in_sizes, int n_in,
                              void* d_out, int out_size) {
    const int*   indices = (const int*)d_in[0];   // int32 (JAX x64 disabled)
    const int*   src  = (const int*)d_in[1];
    const int*   dst  = (const int*)d_in[2];
    const float* w    = (const float*)d_in[3];
    const float* nd   = (const float*)d_in[4];
    const float* W1   = (const float*)d_in[5];
    const float* b1   = (const float*)d_in[6];
    const float* W2   = (const float*)d_in[7];
    const float* b2   = (const float*)d_in[8];
    const float* eps  = (const float*)d_in[9];
    const float* Wc1  = (const float*)d_in[10];
    const float* bc1  = (const float*)d_in[11];
    const float* Wc2  = (const float*)d_in[12];
    const float* bc2  = (const float*)d_in[13];
    const float* Wc3  = (const float*)d_in[14];
    const float* bc3  = (const float*)d_in[15];
    float* out = (float*)d_out;

    cudaFuncSetAttribute(gin_fused<1, 0>, cudaFuncAttributeMaxDynamicSharedMemorySize, GEMM_SMEM);
    cudaFuncSetAttribute(gin_fused<0, 1>, cudaFuncAttributeMaxDynamicSharedMemorySize, GEMM_SMEM);
    cudaFuncSetAttribute(mlp_kernel, cudaFuncAttributeMaxDynamicSharedMemorySize, MLP_SMEM);

    float *h1p, *h2p;
    int *cntp;
    cudaGetSymbolAddress((void**)&h1p, g_h1);
    cudaGetSymbolAddress((void**)&h2p, g_h2);
    cudaGetSymbolAddress((void**)&cntp, g_cnt);

    // CSR build (shared by both layers)
    cudaMemsetAsync(cntp, 0, NN * sizeof(int));
    hist_kernel<<<1024, 256>>>(dst);
    scan_kernel<<<1, SCAN_T>>>();
    scatter_kernel<<<2048, 256>>>(src, dst, w);

    const int gemm_blocks = (NN + 63) / 64;

    gin_fused<1, 0><<<gemm_blocks, 256, GEMM_SMEM>>>(nd, W1, b1, eps, 0, h1p);
    gin_fused<0, 1><<<gemm_blocks, 256, GEMM_SMEM>>>(h1p, W2, b2, eps, 1, h2p);

    mlp_kernel<<<BB / 16, 128, MLP_SMEM>>>(h2p, indices, Wc1, bc1, Wc2, bc2, Wc3, bc3, out);
}

// round 12
// speedup vs baseline: 1.9734x; 1.4940x over previous
#include <cuda_runtime.h>
#include <cuda_bf16.h>
#include <cstdint>

// Problem constants
#define NN 100000
#define EE 1600000
#define HH 128
#define BB 4096
#define CTX 20

// Scratch (allocation-free). 16B alignment for vector paths.
__device__ __align__(16) int  g_cnt[NN];
__device__ __align__(16) int  g_rowptr[NN + 1];
__device__ __align__(16) int  g_cursor[NN];
__device__ __align__(16) int  g_bsum[128];
__device__ __align__(16) int  g_boff[128];
__device__ __align__(16) int2 g_edge[EE];      // {src, w bits} packed
__device__ __align__(16) float g_h1[NN * HH];
__device__ __align__(16) float g_h2[NN * HH];

// ---------- packed f32x2 helpers ----------
__device__ __forceinline__ unsigned long long pk2(float x) {
    unsigned long long r;
    asm("mov.b64 %0, {%1, %1};" : "=l"(r) : "f"(x));
    return r;
}
__device__ __forceinline__ unsigned long long ffma2(unsigned long long a,
                                                    unsigned long long b,
                                                    unsigned long long c) {
    unsigned long long d;
    asm("fma.rn.f32x2 %0, %1, %2, %3;" : "=l"(d) : "l"(a), "l"(b), "l"(c));
    return d;
}
__device__ __forceinline__ void unpk2(unsigned long long v, float& lo, float& hi) {
    asm("mov.b64 {%0, %1}, %2;" : "=f"(lo), "=f"(hi) : "l"(v));
}

// ---------- CSR build: histogram ----------
__global__ void hist_kernel(const int* __restrict__ dst) {
    int i = blockIdx.x * blockDim.x + threadIdx.x;
    int stride = gridDim.x * blockDim.x;
    for (; i < EE; i += stride)
        atomicAdd(&g_cnt[dst[i]], 1);
}

// ---------- CSR build: parallel 3-phase exclusive scan ----------
#define SCAN_BLK 1024
#define SCAN_NB ((NN + SCAN_BLK - 1) / SCAN_BLK)   // 98

__global__ void scanA_kernel() {
    __shared__ int s[SCAN_BLK];
    int tid = threadIdx.x;
    int i = blockIdx.x * SCAN_BLK + tid;
    int v = (i < NN) ? g_cnt[i] : 0;
    s[tid] = v;
    __syncthreads();
    for (int off = 1; off < SCAN_BLK; off <<= 1) {
        int t = (tid >= off) ? s[tid - off] : 0;
        __syncthreads();
        s[tid] += t;
        __syncthreads();
    }
    if (i < NN) g_rowptr[i] = s[tid] - v;            // local exclusive
    if (tid == SCAN_BLK - 1) g_bsum[blockIdx.x] = s[tid];
}

__global__ void scanB_kernel() {
    __shared__ int s[128];
    int tid = threadIdx.x;
    int v = (tid < SCAN_NB) ? g_bsum[tid] : 0;
    s[tid] = v;
    __syncthreads();
    for (int off = 1; off < 128; off <<= 1) {
        int t = (tid >= off) ? s[tid - off] : 0;
        __syncthreads();
        s[tid] += t;
        __syncthreads();
    }
    if (tid < SCAN_NB) g_boff[tid] = s[tid] - v;     // exclusive block offsets
    if (tid == 127) g_rowptr[NN] = s[127];           // grand total (== EE)
}

__global__ void scanC_kernel() {
    int i = blockIdx.x * SCAN_BLK + threadIdx.x;
    if (i < NN) {
        int rv = g_rowptr[i] + g_boff[blockIdx.x];
        g_rowptr[i] = rv;
        g_cursor[i] = rv;
    }
}

// ---------- CSR build: scatter packed edges sorted by dst ----------
__global__ void scatter_kernel(const int* __restrict__ src,
                               const int* __restrict__ dst,
                               const float* __restrict__ w) {
    int i = blockIdx.x * blockDim.x + threadIdx.x;
    int stride = gridDim.x * blockDim.x;
    for (; i < EE; i += stride) {
        int d = dst[i];
        int pos = atomicAdd(&g_cursor[d], 1);
        int2 e; e.x = src[i]; e.y = __float_as_int(w[i]);
        g_edge[pos] = e;
    }
}

// ---------- fused GIN layer: CSR-aggregate + combine + K-chunked GEMM ------
// Block = 64 nodes, 256 threads (8 warps, 8 nodes/warp).
// smem = Zt 33KB + W-chunk 16.9KB -> 4 CTAs/SM (also the reg cap).
#define KCH 32
#define GEMM_SMEM ((128 * 66 + KCH * 132) * 4)

template <int RELU, int ZERO0>
__global__ __launch_bounds__(256, 4)
void gin_fused(const float* __restrict__ x,
               const float* __restrict__ W,
               const float* __restrict__ b,
               const float* __restrict__ eps, int epsidx,
               float* __restrict__ out) {
    extern __shared__ float sm[];
    float* Zt = sm;                 // [128 k][66] nodes transposed, pad 2
    float* Wc = sm + 128 * 66;      // [KCH][132] chunk of W^T, pad 4

    int tid = threadIdx.x;
    int base = blockIdx.x * 64;
    int rows = NN - base; if (rows > 64) rows = 64;
    float ep = 1.0f + __ldg(&eps[epsidx]);

    int lane = tid & 31, wrp = tid >> 5;

    // Prefetch the warp's 9 rowptr values with one coalesced lane load.
    int rp = 0;
    {
        int idx = base + wrp * 8 + lane;
        if (lane <= 8) rp = __ldg(&g_rowptr[idx > NN ? NN : idx]);
    }

#pragma unroll 1
    for (int q = 0; q < 8; q++) {
        int r = wrp * 8 + q;
        int node = base + r;
        int e0 = __shfl_sync(0xffffffffu, rp, q);
        int e1 = __shfl_sync(0xffffffffu, rp, q + 1);
        float rdeg = 1.0f / fmaxf((float)(e1 - e0), 1.0f);

        // early self-row load (independent of edge chain)
        float4 xv = {0.f, 0.f, 0.f, 0.f};
        if (r < rows)
            xv = __ldg(reinterpret_cast<const float4*>(x + (size_t)node * HH) + lane);

        float4 a0 = {0.f,0.f,0.f,0.f}, a1 = a0, a2 = a0, a3 = a0;
        int e = e0;
#pragma unroll 1
        while (e < e1) {
            int take = e1 - e; if (take > 32) take = 32;
            // one coalesced 8B/lane load covers up to 32 edges
            int2 Em = make_int2(0, 0);
            if (lane < take) Em = __ldg(&g_edge[e + lane]);
            int j = 0;
#pragma unroll 1
            for (; j + 4 <= take; j += 4) {
                int   s0 = __shfl_sync(0xffffffffu, Em.x, j);
                int   s1 = __shfl_sync(0xffffffffu, Em.x, j + 1);
                int   s2 = __shfl_sync(0xffffffffu, Em.x, j + 2);
                int   s3 = __shfl_sync(0xffffffffu, Em.x, j + 3);
                float w0 = __int_as_float(__shfl_sync(0xffffffffu, Em.y, j));
                float w1 = __int_as_float(__shfl_sync(0xffffffffu, Em.y, j + 1));
                float w2 = __int_as_float(__shfl_sync(0xffffffffu, Em.y, j + 2));
                float w3 = __int_as_float(__shfl_sync(0xffffffffu, Em.y, j + 3));
                float4 v0 = __ldg(reinterpret_cast<const float4*>(x + (size_t)s0 * HH) + lane);
                float4 v1 = __ldg(reinterpret_cast<const float4*>(x + (size_t)s1 * HH) + lane);
                float4 v2 = __ldg(reinterpret_cast<const float4*>(x + (size_t)s2 * HH) + lane);
                float4 v3 = __ldg(reinterpret_cast<const float4*>(x + (size_t)s3 * HH) + lane);
                a0.x = fmaf(w0, v0.x, a0.x); a0.y = fmaf(w0, v0.y, a0.y);
                a0.z = fmaf(w0, v0.z, a0.z); a0.w = fmaf(w0, v0.w, a0.w);
                a1.x = fmaf(w1, v1.x, a1.x); a1.y = fmaf(w1, v1.y, a1.y);
                a1.z = fmaf(w1, v1.z, a1.z); a1.w = fmaf(w1, v1.w, a1.w);
                a2.x = fmaf(w2, v2.x, a2.x); a2.y = fmaf(w2, v2.y, a2.y);
                a2.z = fmaf(w2, v2.z, a2.z); a2.w = fmaf(w2, v2.w, a2.w);
                a3.x = fmaf(w3, v3.x, a3.x); a3.y = fmaf(w3, v3.y, a3.y);
                a3.z = fmaf(w3, v3.z, a3.z); a3.w = fmaf(w3, v3.w, a3.w);
            }
#pragma unroll 1
            for (; j < take; j++) {
                int   s0 = __shfl_sync(0xffffffffu, Em.x, j);
                float w0 = __int_as_float(__shfl_sync(0xffffffffu, Em.y, j));
                float4 v0 = __ldg(reinterpret_cast<const float4*>(x + (size_t)s0 * HH) + lane);
                a0.x = fmaf(w0, v0.x, a0.x); a0.y = fmaf(w0, v0.y, a0.y);
                a0.z = fmaf(w0, v0.z, a0.z); a0.w = fmaf(w0, v0.w, a0.w);
            }
            e += take;
        }

        float z0 = fmaf(ep, xv.x, ((a0.x + a1.x) + (a2.x + a3.x)) * rdeg);
        float z1 = fmaf(ep, xv.y, ((a0.y + a1.y) + (a2.y + a3.y)) * rdeg);
        float z2 = fmaf(ep, xv.z, ((a0.z + a1.z) + (a2.z + a3.z)) * rdeg);
        float z3 = fmaf(ep, xv.w, ((a0.w + a1.w) + (a2.w + a3.w)) * rdeg);

        int k0 = lane * 4;
        Zt[(k0 + 0) * 66 + r] = z0;
        Zt[(k0 + 1) * 66 + r] = z1;
        Zt[(k0 + 2) * 66 + r] = z2;
        Zt[(k0 + 3) * 66 + r] = z3;
    }
    __syncthreads();

    // GEMM: K streamed in 4 chunks of 32; 8x4 register tile, packed f32x2
    int tx = tid & 31, ty = tid >> 5;
    int c0 = tx * 4, r0 = ty * 8;
    unsigned long long acc[4][4];
#pragma unroll
    for (int p = 0; p < 4; p++)
#pragma unroll
        for (int j = 0; j < 4; j++) acc[p][j] = 0ULL;

    for (int kc = 0; kc < 128 / KCH; kc++) {
        for (int i = tid; i < 128 * KCH; i += 256) {
            int c = i >> 5, kk = i & 31;
            Wc[kk * 132 + c] = W[c * 128 + kc * KCH + kk];
        }
        __syncthreads();
#pragma unroll 4
        for (int kk = 0; kk < KCH; kk++) {
            int k = kc * KCH + kk;
            float4 wv = *reinterpret_cast<const float4*>(&Wc[kk * 132 + c0]);
            unsigned long long b0 = pk2(wv.x), b1 = pk2(wv.y), b2 = pk2(wv.z), b3 = pk2(wv.w);
            const unsigned long long* az =
                reinterpret_cast<const unsigned long long*>(&Zt[k * 66 + r0]);
            unsigned long long a0 = az[0], a1 = az[1], a2 = az[2], a3 = az[3];
            acc[0][0] = ffma2(a0, b0, acc[0][0]); acc[0][1] = ffma2(a0, b1, acc[0][1]);
            acc[0][2] = ffma2(a0, b2, acc[0][2]); acc[0][3] = ffma2(a0, b3, acc[0][3]);
            acc[1][0] = ffma2(a1, b0, acc[1][0]); acc[1][1] = ffma2(a1, b1, acc[1][1]);
            acc[1][2] = ffma2(a1, b2, acc[1][2]); acc[1][3] = ffma2(a1, b3, acc[1][3]);
            acc[2][0] = ffma2(a2, b0, acc[2][0]); acc[2][1] = ffma2(a2, b1, acc[2][1]);
            acc[2][2] = ffma2(a2, b2, acc[2][2]); acc[2][3] = ffma2(a2, b3, acc[2][3]);
            acc[3][0] = ffma2(a3, b0, acc[3][0]); acc[3][1] = ffma2(a3, b1, acc[3][1]);
            acc[3][2] = ffma2(a3, b2, acc[3][2]); acc[3][3] = ffma2(a3, b3, acc[3][3]);
        }
        __syncthreads();
    }

    float4 bv = *reinterpret_cast<const float4*>(&b[c0]);
    float bb[4] = {bv.x, bv.y, bv.z, bv.w};
#pragma unroll
    for (int p = 0; p < 4; p++) {
        float lo[4], hi[4];
#pragma unroll
        for (int j = 0; j < 4; j++) unpk2(acc[p][j], lo[j], hi[j]);
        int r = r0 + 2 * p;
#pragma unroll
        for (int half = 0; half < 2; half++) {
            int rr = r + half;
            if (rr < rows) {
                int node = base + rr;
                float v0 = (half ? hi[0] : lo[0]) + bb[0];
                float v1 = (half ? hi[1] : lo[1]) + bb[1];
                float v2 = (half ? hi[2] : lo[2]) + bb[2];
                float v3 = (half ? hi[3] : lo[3]) + bb[3];
                if (RELU) { v0 = fmaxf(v0, 0.f); v1 = fmaxf(v1, 0.f);
                            v2 = fmaxf(v2, 0.f); v3 = fmaxf(v3, 0.f); }
                if (ZERO0 && node == 0) { v0 = v1 = v2 = v3 = 0.f; }
                float4 o; o.x = v0; o.y = v1; o.z = v2; o.w = v3;
                *reinterpret_cast<float4*>(out + (size_t)node * HH + c0) = o;
            }
        }
    }
}

// ---------- MLP head: 16 batch rows per block, 256 threads ----------
// indices are INT32 (JAX x64 disabled downcasts the declared int64).
#define MLP_IND_BYTES 1536
#define MLP_SMEM (MLP_IND_BYTES + (384 * 18 + 128 * 65 + 16 * 128 + 64 * 129 + 16 * 64) * 4)

__global__ __launch_bounds__(256)
void mlp_kernel(const float* __restrict__ x,
                const int* __restrict__ ind,
                const float* __restrict__ Wc1, const float* __restrict__ bc1,
                const float* __restrict__ Wc2, const float* __restrict__ bc2,
                const float* __restrict__ Wc3, const float* __restrict__ bc3,
                float* __restrict__ out) {
    extern __shared__ char smraw[];
    int* inds = reinterpret_cast<int*>(smraw);
    float* Yt   = reinterpret_cast<float*>(smraw + MLP_IND_BYTES); // [384][18]
    float* Wcs  = Yt + 384 * 18;                                   // [128][65]
    float* h1s  = Wcs + 128 * 65;                                  // [16][128]
    float* Wc2s = h1s + 16 * 128;                                  // [64][129]
    float* h2s  = Wc2s + 64 * 129;                                 // [16][64]

    int tid = threadIdx.x;
    int rb0 = blockIdx.x * 16;
    int c = tid & 127;           // channel / feature index
    int half = tid >> 7;         // 0 or 1: row-half

    for (int i = tid; i < 16 * 23; i += 256)
        inds[i] = ind[(size_t)rb0 * 23 + i];
    __syncthreads();

    // gather: Yt[k][r], rows split across the two halves
    for (int rr = 0; rr < 8; rr++) {
        int r = half * 8 + rr;
        int i0 = inds[r * 23 + 0];
        int i1 = inds[r * 23 + 1];
        Yt[c * 18 + r]         = __ldg(&x[(size_t)i0 * HH + c]);
        Yt[(128 + c) * 18 + r] = __ldg(&x[(size_t)i1 * HH + c]);
        float s = 0.0f; int cnt = 0;
#pragma unroll
        for (int j = 0; j < CTX; j++) {
            int cj = inds[r * 23 + 3 + j];
            s += __ldg(&x[(size_t)cj * HH + c]);
            cnt += (cj > 0);
        }
        if (cnt < 1) cnt = 1;
        Yt[(256 + c) * 18 + r] = s * (1.0f / (float)cnt);
    }
    __syncthreads();

    // C1: 384 -> 128, relu. Thread (c, half) does 4 row-pairs.
    int pbase = half * 4;
    unsigned long long acc2[4];
#pragma unroll
    for (int p = 0; p < 4; p++) acc2[p] = 0ULL;

    for (int kc = 0; kc < 6; kc++) {
        for (int i = tid; i < 128 * 64; i += 256) {
            int cc = i >> 6, kk = i & 63;
            Wcs[cc * 65 + kk] = Wc1[(size_t)cc * 384 + kc * 64 + kk];
        }
        __syncthreads();
#pragma unroll 4
        for (int kk = 0; kk < 64; kk++) {
            int k = kc * 64 + kk;
            unsigned long long w2 = pk2(Wcs[c * 65 + kk]);
            const unsigned long long* ay =
                reinterpret_cast<const unsigned long long*>(&Yt[k * 18]);
#pragma unroll
            for (int p = 0; p < 4; p++) acc2[p] = ffma2(ay[pbase + p], w2, acc2[p]);
        }
        __syncthreads();
    }
    {
        float bb = __ldg(&bc1[c]);
#pragma unroll
        for (int p = 0; p < 4; p++) {
            float lo, hi;
            unpk2(acc2[p], lo, hi);
            int pr = pbase + p;
            h1s[(2 * pr) * 128 + c]     = fmaxf(lo + bb, 0.0f);
            h1s[(2 * pr + 1) * 128 + c] = fmaxf(hi + bb, 0.0f);
        }
    }
    __syncthreads();

    // C2: 128 -> 64, relu. 4 threads per channel, 4 rows each.
    for (int i = tid; i < 64 * 128; i += 256) {
        int cc = i >> 7, kk = i & 127;
        Wc2s[cc * 129 + kk] = Wc2[i];
    }
    __syncthreads();
    {
        int c2 = tid & 63;
        int quarter = tid >> 6;  // 0..3
        float acc[4];
#pragma unroll
        for (int q = 0; q < 4; q++) acc[q] = 0.0f;
#pragma unroll 4
        for (int k = 0; k < 128; k++) {
            float wv = Wc2s[c2 * 129 + k];
#pragma unroll
            for (int q = 0; q < 4; q++)
                acc[q] += h1s[(quarter * 4 + q) * 128 + k] * wv;
        }
        float b2v = __ldg(&bc2[c2]);
#pragma unroll
        for (int q = 0; q < 4; q++)
            h2s[(quarter * 4 + q) * 64 + c2] = fmaxf(acc[q] + b2v, 0.0f);
    }
    __syncthreads();

    // C3: 64 -> 1
    if (tid < 16) {
        float a = __ldg(&bc3[0]);
#pragma unroll 4
        for (int k = 0; k < 64; k++)
            a += h2s[tid * 64 + k] * __ldg(&Wc3[k]);
        out[rb0 + tid] = a;
    }
}

// ---------- launcher ----------
extern "C" void kernel_launch(void* const* d_in, const int* in_sizes, int n_in,
                              void* d_out, int out_size) {
    const int*   indices = (const int*)d_in[0];   // int32 (JAX x64 disabled)
    const int*   src  = (const int*)d_in[1];
    const int*   dst  = (const int*)d_in[2];
    const float* w    = (const float*)d_in[3];
    const float* nd   = (const float*)d_in[4];
    const float* W1   = (const float*)d_in[5];
    const float* b1   = (const float*)d_in[6];
    const float* W2   = (const float*)d_in[7];
    const float* b2   = (const float*)d_in[8];
    const float* eps  = (const float*)d_in[9];
    const float* Wc1  = (const float*)d_in[10];
    const float* bc1  = (const float*)d_in[11];
    const float* Wc2  = (const float*)d_in[12];
    const float* bc2  = (const float*)d_in[13];
    const float* Wc3  = (const float*)d_in[14];
    const float* bc3  = (const float*)d_in[15];
    float* out = (float*)d_out;

    cudaFuncSetAttribute(gin_fused<1, 0>, cudaFuncAttributeMaxDynamicSharedMemorySize, GEMM_SMEM);
    cudaFuncSetAttribute(gin_fused<0, 1>, cudaFuncAttributeMaxDynamicSharedMemorySize, GEMM_SMEM);
    cudaFuncSetAttribute(mlp_kernel, cudaFuncAttributeMaxDynamicSharedMemorySize, MLP_SMEM);

    float *h1p, *h2p;
    int *cntp;
    cudaGetSymbolAddress((void**)&h1p, g_h1);
    cudaGetSymbolAddress((void**)&h2p, g_h2);
    cudaGetSymbolAddress((void**)&cntp, g_cnt);

    // CSR build (shared by both layers)
    cudaMemsetAsync(cntp, 0, NN * sizeof(int));
    hist_kernel<<<2048, 256>>>(dst);
    scanA_kernel<<<SCAN_NB, SCAN_BLK>>>();
    scanB_kernel<<<1, 128>>>();
    scanC_kernel<<<SCAN_NB, SCAN_BLK>>>();
    scatter_kernel<<<2048, 256>>>(src, dst, w);

    const int gemm_blocks = (NN + 63) / 64;

    gin_fused<1, 0><<<gemm_blocks, 256, GEMM_SMEM>>>(nd, W1, b1, eps, 0, h1p);
    gin_fused<0, 1><<<gemm_blocks, 256, GEMM_SMEM>>>(h1p, W2, b2, eps, 1, h2p);

    mlp_kernel<<<BB / 16, 256, MLP_SMEM>>>(h2p, indices, Wc1, bc1, Wc2, bc2, Wc3, bc3, out);
}

// round 17
// speedup vs baseline: 1.9770x; 1.0018x over previous
#include <cuda_runtime.h>
#include <cuda_bf16.h>
#include <cstdint>

// Problem constants
#define NN 100000
#define EE 1600000
#define HH 128
#define BB 4096
#define CTX 20

// Scratch (allocation-free). 16B alignment for vector paths.
__device__ __align__(16) int  g_cnt[NN];
__device__ __align__(16) int  g_rowptr[NN + 1];
__device__ __align__(16) int  g_cursor[NN];
__device__ __align__(16) int  g_bsum[128];
__device__ __align__(16) int  g_boff[128];
__device__ __align__(16) int2 g_edge[EE];      // {src, w bits} packed
__device__ __align__(16) float g_h1[NN * HH];
__device__ __align__(16) float g_h2[NN * HH];

// ---------- packed f32x2 helpers ----------
__device__ __forceinline__ unsigned long long pk2(float x) {
    unsigned long long r;
    asm("mov.b64 %0, {%1, %1};" : "=l"(r) : "f"(x));
    return r;
}
__device__ __forceinline__ unsigned long long ffma2(unsigned long long a,
                                                    unsigned long long b,
                                                    unsigned long long c) {
    unsigned long long d;
    asm("fma.rn.f32x2 %0, %1, %2, %3;" : "=l"(d) : "l"(a), "l"(b), "l"(c));
    return d;
}
__device__ __forceinline__ void unpk2(unsigned long long v, float& lo, float& hi) {
    asm("mov.b64 {%0, %1}, %2;" : "=f"(lo), "=f"(hi) : "l"(v));
}

// ---------- CSR build: histogram (4 edges / iteration) ----------
__global__ void hist_kernel(const int* __restrict__ dst) {
    int i = blockIdx.x * blockDim.x + threadIdx.x;
    int stride = gridDim.x * blockDim.x;
    const int4* d4 = reinterpret_cast<const int4*>(dst);
    for (; i < EE / 4; i += stride) {
        int4 d = __ldg(&d4[i]);
        atomicAdd(&g_cnt[d.x], 1);
        atomicAdd(&g_cnt[d.y], 1);
        atomicAdd(&g_cnt[d.z], 1);
        atomicAdd(&g_cnt[d.w], 1);
    }
}

// ---------- CSR build: parallel 3-phase exclusive scan ----------
#define SCAN_BLK 1024
#define SCAN_NB ((NN + SCAN_BLK - 1) / SCAN_BLK)   // 98

__global__ void scanA_kernel() {
    __shared__ int s[SCAN_BLK];
    int tid = threadIdx.x;
    int i = blockIdx.x * SCAN_BLK + tid;
    int v = (i < NN) ? g_cnt[i] : 0;
    s[tid] = v;
    __syncthreads();
    for (int off = 1; off < SCAN_BLK; off <<= 1) {
        int t = (tid >= off) ? s[tid - off] : 0;
        __syncthreads();
        s[tid] += t;
        __syncthreads();
    }
    if (i < NN) g_rowptr[i] = s[tid] - v;            // local exclusive
    if (tid == SCAN_BLK - 1) g_bsum[blockIdx.x] = s[tid];
}

__global__ void scanB_kernel() {
    __shared__ int s[128];
    int tid = threadIdx.x;
    int v = (tid < SCAN_NB) ? g_bsum[tid] : 0;
    s[tid] = v;
    __syncthreads();
    for (int off = 1; off < 128; off <<= 1) {
        int t = (tid >= off) ? s[tid - off] : 0;
        __syncthreads();
        s[tid] += t;
        __syncthreads();
    }
    if (tid < SCAN_NB) g_boff[tid] = s[tid] - v;     // exclusive block offsets
    if (tid == 127) g_rowptr[NN] = s[127];           // grand total (== EE)
}

__global__ void scanC_kernel() {
    int i = blockIdx.x * SCAN_BLK + threadIdx.x;
    if (i < NN) {
        int rv = g_rowptr[i] + g_boff[blockIdx.x];
        g_rowptr[i] = rv;
        g_cursor[i] = rv;
    }
}

// ---------- CSR build: scatter packed edges (4 edges / iteration) ----------
__global__ void scatter_kernel(const int* __restrict__ src,
                               const int* __restrict__ dst,
                               const float* __restrict__ w) {
    int i = blockIdx.x * blockDim.x + threadIdx.x;
    int stride = gridDim.x * blockDim.x;
    const int4* s4p = reinterpret_cast<const int4*>(src);
    const int4* d4p = reinterpret_cast<const int4*>(dst);
    const float4* w4p = reinterpret_cast<const float4*>(w);
    for (; i < EE / 4; i += stride) {
        int4 s = __ldg(&s4p[i]);
        int4 d = __ldg(&d4p[i]);
        float4 ww = __ldg(&w4p[i]);
        int p0 = atomicAdd(&g_cursor[d.x], 1);
        int p1 = atomicAdd(&g_cursor[d.y], 1);
        int p2 = atomicAdd(&g_cursor[d.z], 1);
        int p3 = atomicAdd(&g_cursor[d.w], 1);
        g_edge[p0] = make_int2(s.x, __float_as_int(ww.x));
        g_edge[p1] = make_int2(s.y, __float_as_int(ww.y));
        g_edge[p2] = make_int2(s.z, __float_as_int(ww.z));
        g_edge[p3] = make_int2(s.w, __float_as_int(ww.w));
    }
}

// ---------- fused GIN layer: CSR-aggregate + combine + K-chunked GEMM ------
// Block = 64 nodes, 256 threads (8 warps, 8 nodes/warp in agg).
// GEMM warp tile = 32 rows x 32 cols (4 row-groups x 8 col-groups per warp):
// per warp-k smem cost = 4 wf (Z, 4-distinct-addr LDS.64) + 1 wf (contig 128B
// LDS.128 of W) = 5 wf vs 8 for the old 8x128 warp tile.
#define KCH 32
#define GEMM_SMEM ((128 * 66 + KCH * 132) * 4)

template <int RELU, int ZERO0>
__global__ __launch_bounds__(256, 4)
void gin_fused(const float* __restrict__ x,
               const float* __restrict__ W,
               const float* __restrict__ b,
               const float* __restrict__ eps, int epsidx,
               float* __restrict__ out) {
    extern __shared__ float sm[];
    float* Zt = sm;                 // [128 k][66] nodes transposed, pad 2
    float* Wc = sm + 128 * 66;      // [KCH][132] chunk of W^T, pad 4

    int tid = threadIdx.x;
    int base = blockIdx.x * 64;
    int rows = NN - base; if (rows > 64) rows = 64;
    float ep = 1.0f + __ldg(&eps[epsidx]);

    int lane = tid & 31, wrp = tid >> 5;

    // Prefetch the warp's 9 rowptr values with one coalesced lane load.
    int rp = 0;
    {
        int idx = base + wrp * 8 + lane;
        if (lane <= 8) rp = __ldg(&g_rowptr[idx > NN ? NN : idx]);
    }

#pragma unroll 1
    for (int q = 0; q < 8; q++) {
        int r = wrp * 8 + q;
        int node = base + r;
        int e0 = __shfl_sync(0xffffffffu, rp, q);
        int e1 = __shfl_sync(0xffffffffu, rp, q + 1);
        float rdeg = 1.0f / fmaxf((float)(e1 - e0), 1.0f);

        // early self-row load (independent of edge chain)
        float4 xv = {0.f, 0.f, 0.f, 0.f};
        if (r < rows)
            xv = __ldg(reinterpret_cast<const float4*>(x + (size_t)node * HH) + lane);

        float4 a0 = {0.f,0.f,0.f,0.f}, a1 = a0, a2 = a0, a3 = a0;
        int e = e0;
#pragma unroll 1
        while (e < e1) {
            int take = e1 - e; if (take > 32) take = 32;
            // one coalesced 8B/lane load covers up to 32 edges
            int2 Em = make_int2(0, 0);
            if (lane < take) Em = __ldg(&g_edge[e + lane]);
            int j = 0;
#pragma unroll 1
            for (; j + 4 <= take; j += 4) {
                int   s0 = __shfl_sync(0xffffffffu, Em.x, j);
                int   s1 = __shfl_sync(0xffffffffu, Em.x, j + 1);
                int   s2 = __shfl_sync(0xffffffffu, Em.x, j + 2);
                int   s3 = __shfl_sync(0xffffffffu, Em.x, j + 3);
                float w0 = __int_as_float(__shfl_sync(0xffffffffu, Em.y, j));
                float w1 = __int_as_float(__shfl_sync(0xffffffffu, Em.y, j + 1));
                float w2 = __int_as_float(__shfl_sync(0xffffffffu, Em.y, j + 2));
                float w3 = __int_as_float(__shfl_sync(0xffffffffu, Em.y, j + 3));
                float4 v0 = __ldg(reinterpret_cast<const float4*>(x + (size_t)s0 * HH) + lane);
                float4 v1 = __ldg(reinterpret_cast<const float4*>(x + (size_t)s1 * HH) + lane);
                float4 v2 = __ldg(reinterpret_cast<const float4*>(x + (size_t)s2 * HH) + lane);
                float4 v3 = __ldg(reinterpret_cast<const float4*>(x + (size_t)s3 * HH) + lane);
                a0.x = fmaf(w0, v0.x, a0.x); a0.y = fmaf(w0, v0.y, a0.y);
                a0.z = fmaf(w0, v0.z, a0.z); a0.w = fmaf(w0, v0.w, a0.w);
                a1.x = fmaf(w1, v1.x, a1.x); a1.y = fmaf(w1, v1.y, a1.y);
                a1.z = fmaf(w1, v1.z, a1.z); a1.w = fmaf(w1, v1.w, a1.w);
                a2.x = fmaf(w2, v2.x, a2.x); a2.y = fmaf(w2, v2.y, a2.y);
                a2.z = fmaf(w2, v2.z, a2.z); a2.w = fmaf(w2, v2.w, a2.w);
                a3.x = fmaf(w3, v3.x, a3.x); a3.y = fmaf(w3, v3.y, a3.y);
                a3.z = fmaf(w3, v3.z, a3.z); a3.w = fmaf(w3, v3.w, a3.w);
            }
#pragma unroll 1
            for (; j < take; j++) {
                int   s0 = __shfl_sync(0xffffffffu, Em.x, j);
                float w0 = __int_as_float(__shfl_sync(0xffffffffu, Em.y, j));
                float4 v0 = __ldg(reinterpret_cast<const float4*>(x + (size_t)s0 * HH) + lane);
                a0.x = fmaf(w0, v0.x, a0.x); a0.y = fmaf(w0, v0.y, a0.y);
                a0.z = fmaf(w0, v0.z, a0.z); a0.w = fmaf(w0, v0.w, a0.w);
            }
            e += take;
        }

        float z0 = fmaf(ep, xv.x, ((a0.x + a1.x) + (a2.x + a3.x)) * rdeg);
        float z1 = fmaf(ep, xv.y, ((a0.y + a1.y) + (a2.y + a3.y)) * rdeg);
        float z2 = fmaf(ep, xv.z, ((a0.z + a1.z) + (a2.z + a3.z)) * rdeg);
        float z3 = fmaf(ep, xv.w, ((a0.w + a1.w) + (a2.w + a3.w)) * rdeg);

        int k0 = lane * 4;
        Zt[(k0 + 0) * 66 + r] = z0;
        Zt[(k0 + 1) * 66 + r] = z1;
        Zt[(k0 + 2) * 66 + r] = z2;
        Zt[(k0 + 3) * 66 + r] = z3;
    }
    __syncthreads();

    // GEMM: warp tile 32x32; lane tile 8 rows x 4 cols.
    int wrow = (tid >> 5) >> 2;        // 0..1  (warp row-group: 32 rows each)
    int wcol = (tid >> 5) & 3;         // 0..3  (warp col-group: 32 cols each)
    int rg = lane >> 3;                // 0..3  row-group within warp (8 rows)
    int cg = lane & 7;                 // 0..7  col-group within warp (4 cols)
    int r0 = wrow * 32 + rg * 8;
    int c0 = wcol * 32 + cg * 4;

    unsigned long long acc[4][4];
#pragma unroll
    for (int p = 0; p < 4; p++)
#pragma unroll
        for (int j = 0; j < 4; j++) acc[p][j] = 0ULL;

    for (int kc = 0; kc < 128 / KCH; kc++) {
        for (int i = tid; i < 128 * KCH; i += 256) {
            int c = i >> 5, kk = i & 31;
            Wc[kk * 132 + c] = W[c * 128 + kc * KCH + kk];
        }
        __syncthreads();
#pragma unroll 4
        for (int kk = 0; kk < KCH; kk++) {
            int k = kc * KCH + kk;
            float4 wv = *reinterpret_cast<const float4*>(&Wc[kk * 132 + c0]);
            unsigned long long b0 = pk2(wv.x), b1 = pk2(wv.y), b2 = pk2(wv.z), b3 = pk2(wv.w);
            const unsigned long long* az =
                reinterpret_cast<const unsigned long long*>(&Zt[k * 66 + r0]);
            unsigned long long a0 = az[0], a1 = az[1], a2 = az[2], a3 = az[3];
            acc[0][0] = ffma2(a0, b0, acc[0][0]); acc[0][1] = ffma2(a0, b1, acc[0][1]);
            acc[0][2] = ffma2(a0, b2, acc[0][2]); acc[0][3] = ffma2(a0, b3, acc[0][3]);
            acc[1][0] = ffma2(a1, b0, acc[1][0]); acc[1][1] = ffma2(a1, b1, acc[1][1]);
            acc[1][2] = ffma2(a1, b2, acc[1][2]); acc[1][3] = ffma2(a1, b3, acc[1][3]);
            acc[2][0] = ffma2(a2, b0, acc[2][0]); acc[2][1] = ffma2(a2, b1, acc[2][1]);
            acc[2][2] = ffma2(a2, b2, acc[2][2]); acc[2][3] = ffma2(a2, b3, acc[2][3]);
            acc[3][0] = ffma2(a3, b0, acc[3][0]); acc[3][1] = ffma2(a3, b1, acc[3][1]);
            acc[3][2] = ffma2(a3, b2, acc[3][2]); acc[3][3] = ffma2(a3, b3, acc[3][3]);
        }
        __syncthreads();
    }

    float4 bv = *reinterpret_cast<const float4*>(&b[c0]);
    float bb[4] = {bv.x, bv.y, bv.z, bv.w};
#pragma unroll
    for (int p = 0; p < 4; p++) {
        float lo[4], hi[4];
#pragma unroll
        for (int j = 0; j < 4; j++) unpk2(acc[p][j], lo[j], hi[j]);
        int r = r0 + 2 * p;
#pragma unroll
        for (int half = 0; half < 2; half++) {
            int rr = r + half;
            if (rr < rows) {
                int node = base + rr;
                float v0 = (half ? hi[0] : lo[0]) + bb[0];
                float v1 = (half ? hi[1] : lo[1]) + bb[1];
                float v2 = (half ? hi[2] : lo[2]) + bb[2];
                float v3 = (half ? hi[3] : lo[3]) + bb[3];
                if (RELU) { v0 = fmaxf(v0, 0.f); v1 = fmaxf(v1, 0.f);
                            v2 = fmaxf(v2, 0.f); v3 = fmaxf(v3, 0.f); }
                if (ZERO0 && node == 0) { v0 = v1 = v2 = v3 = 0.f; }
                float4 o; o.x = v0; o.y = v1; o.z = v2; o.w = v3;
                *reinterpret_cast<float4*>(out + (size_t)node * HH + c0) = o;
            }
        }
    }
}

// ---------- MLP head: 16 batch rows per block, 256 threads ----------
// indices are INT32 (JAX x64 disabled downcasts the declared int64).
#define MLP_IND_BYTES 1536
#define MLP_SMEM (MLP_IND_BYTES + (384 * 18 + 128 * 65 + 16 * 128 + 64 * 129 + 16 * 64) * 4)

__global__ __launch_bounds__(256)
void mlp_kernel(const float* __restrict__ x,
                const int* __restrict__ ind,
                const float* __restrict__ Wc1, const float* __restrict__ bc1,
                const float* __restrict__ Wc2, const float* __restrict__ bc2,
                const float* __restrict__ Wc3, const float* __restrict__ bc3,
                float* __restrict__ out) {
    extern __shared__ char smraw[];
    int* inds = reinterpret_cast<int*>(smraw);
    float* Yt   = reinterpret_cast<float*>(smraw + MLP_IND_BYTES); // [384][18]
    float* Wcs  = Yt + 384 * 18;                                   // [128][65]
    float* h1s  = Wcs + 128 * 65;                                  // [16][128]
    float* Wc2s = h1s + 16 * 128;                                  // [64][129]
    float* h2s  = Wc2s + 64 * 129;                                 // [16][64]

    int tid = threadIdx.x;
    int rb0 = blockIdx.x * 16;
    int c = tid & 127;           // channel / feature index
    int half = tid >> 7;         // 0 or 1: row-half

    for (int i = tid; i < 16 * 23; i += 256)
        inds[i] = ind[(size_t)rb0 * 23 + i];
    __syncthreads();

    // gather: Yt[k][r], rows split across the two halves
    for (int rr = 0; rr < 8; rr++) {
        int r = half * 8 + rr;
        int i0 = inds[r * 23 + 0];
        int i1 = inds[r * 23 + 1];
        Yt[c * 18 + r]         = __ldg(&x[(size_t)i0 * HH + c]);
        Yt[(128 + c) * 18 + r] = __ldg(&x[(size_t)i1 * HH + c]);
        float s = 0.0f; int cnt = 0;
#pragma unroll
        for (int j = 0; j < CTX; j++) {
            int cj = inds[r * 23 + 3 + j];
            s += __ldg(&x[(size_t)cj * HH + c]);
            cnt += (cj > 0);
        }
        if (cnt < 1) cnt = 1;
        Yt[(256 + c) * 18 + r] = s * (1.0f / (float)cnt);
    }
    __syncthreads();

    // C1: 384 -> 128, relu. Thread (c, half) does 4 row-pairs.
    int pbase = half * 4;
    unsigned long long acc2[4];
#pragma unroll
    for (int p = 0; p < 4; p++) acc2[p] = 0ULL;

    for (int kc = 0; kc < 6; kc++) {
        for (int i = tid; i < 128 * 64; i += 256) {
            int cc = i >> 6, kk = i & 63;
            Wcs[cc * 65 + kk] = Wc1[(size_t)cc * 384 + kc * 64 + kk];
        }
        __syncthreads();
#pragma unroll 4
        for (int kk = 0; kk < 64; kk++) {
            int k = kc * 64 + kk;
            unsigned long long w2 = pk2(Wcs[c * 65 + kk]);
            const unsigned long long* ay =
                reinterpret_cast<const unsigned long long*>(&Yt[k * 18]);
#pragma unroll
            for (int p = 0; p < 4; p++) acc2[p] = ffma2(ay[pbase + p], w2, acc2[p]);
        }
        __syncthreads();
    }
    {
        float bb = __ldg(&bc1[c]);
#pragma unroll
        for (int p = 0; p < 4; p++) {
            float lo, hi;
            unpk2(acc2[p], lo, hi);
            int pr = pbase + p;
            h1s[(2 * pr) * 128 + c]     = fmaxf(lo + bb, 0.0f);
            h1s[(2 * pr + 1) * 128 + c] = fmaxf(hi + bb, 0.0f);
        }
    }
    __syncthreads();

    // C2: 128 -> 64, relu. 4 threads per channel, 4 rows each.
    for (int i = tid; i < 64 * 128; i += 256) {
        int cc = i >> 7, kk = i & 127;
        Wc2s[cc * 129 + kk] = Wc2[i];
    }
    __syncthreads();
    {
        int c2 = tid & 63;
        int quarter = tid >> 6;  // 0..3
        float acc[4];
#pragma unroll
        for (int q = 0; q < 4; q++) acc[q] = 0.0f;
#pragma unroll 4
        for (int k = 0; k < 128; k++) {
            float wv = Wc2s[c2 * 129 + k];
#pragma unroll
            for (int q = 0; q < 4; q++)
                acc[q] += h1s[(quarter * 4 + q) * 128 + k] * wv;
        }
        float b2v = __ldg(&bc2[c2]);
#pragma unroll
        for (int q = 0; q < 4; q++)
            h2s[(quarter * 4 + q) * 64 + c2] = fmaxf(acc[q] + b2v, 0.0f);
    }
    __syncthreads();

    // C3: 64 -> 1
    if (tid < 16) {
        float a = __ldg(&bc3[0]);
#pragma unroll 4
        for (int k = 0; k < 64; k++)
            a += h2s[tid * 64 + k] * __ldg(&Wc3[k]);
        out[rb0 + tid] = a;
    }
}

// ---------- launcher ----------
extern "C" void kernel_launch(void* const* d_in, const int* in_sizes, int n_in,
                              void* d_out, int out_size) {
    const int*   indices = (const int*)d_in[0];   // int32 (JAX x64 disabled)
    const int*   src  = (const int*)d_in[1];
    const int*   dst  = (const int*)d_in[2];
    const float* w    = (const float*)d_in[3];
    const float* nd   = (const float*)d_in[4];
    const float* W1   = (const float*)d_in[5];
    const float* b1   = (const float*)d_in[6];
    const float* W2   = (const float*)d_in[7];
    const float* b2   = (const float*)d_in[8];
    const float* eps  = (const float*)d_in[9];
    const float* Wc1  = (const float*)d_in[10];
    const float* bc1  = (const float*)d_in[11];
    const float* Wc2  = (const float*)d_in[12];
    const float* bc2  = (const float*)d_in[13];
    const float* Wc3  = (const float*)d_in[14];
    const float* bc3  = (const float*)d_in[15];
    float* out = (float*)d_out;

    cudaFuncSetAttribute(gin_fused<1, 0>, cudaFuncAttributeMaxDynamicSharedMemorySize, GEMM_SMEM);
    cudaFuncSetAttribute(gin_fused<0, 1>, cudaFuncAttributeMaxDynamicSharedMemorySize, GEMM_SMEM);
    cudaFuncSetAttribute(mlp_kernel, cudaFuncAttributeMaxDynamicSharedMemorySize, MLP_SMEM);

    float *h1p, *h2p;
    int *cntp;
    cudaGetSymbolAddress((void**)&h1p, g_h1);
    cudaGetSymbolAddress((void**)&h2p, g_h2);
    cudaGetSymbolAddress((void**)&cntp, g_cnt);

    // CSR build (shared by both layers)
    cudaMemsetAsync(cntp, 0, NN * sizeof(int));
    hist_kernel<<<1024, 256>>>(dst);
    scanA_kernel<<<SCAN_NB, SCAN_BLK>>>();
    scanB_kernel<<<1, 128>>>();
    scanC_kernel<<<SCAN_NB, SCAN_BLK>>>();
    scatter_kernel<<<1024, 256>>>(src, dst, w);

    const int gemm_blocks = (NN + 63) / 64;

    gin_fused<1, 0><<<gemm_blocks, 256, GEMM_SMEM>>>(nd, W1, b1, eps, 0, h1p);
    gin_fused<0, 1><<<gemm_blocks, 256, GEMM_SMEM>>>(h1p, W2, b2, eps, 1, h2p);

    mlp_kernel<<<BB / 16, 256, MLP_SMEM>>>(h2p, indices, Wc1, bc1, Wc2, bc2, Wc3, bc3, out);
}